// round 2
// baseline (speedup 1.0000x reference)
#include <cuda_runtime.h>
#include <math.h>

#define BB 4
#define SS 2048
#define DD 128
#define EPSV 1e-5f

// scratch (no allocations allowed)
__device__ float g_qnorm[BB * SS];
__device__ float g_knorm[BB * SS];

// ---------------------------------------------------------------------------
// Kernel 1: row norms ||q||^2, ||k||^2. One warp per row, float4 loads.
// ---------------------------------------------------------------------------
__global__ __launch_bounds__(256) void norms_kernel(const float* __restrict__ q,
                                                    const float* __restrict__ k) {
    int warp = (blockIdx.x * blockDim.x + threadIdx.x) >> 5;
    int lane = threadIdx.x & 31;
    const int R = BB * SS;
    if (warp >= 2 * R) return;
    const float* src = (warp < R) ? (q + (size_t)warp * DD)
                                  : (k + (size_t)(warp - R) * DD);
    float4 v = ((const float4*)src)[lane];
    float s = v.x * v.x + v.y * v.y + v.z * v.z + v.w * v.w;
#pragma unroll
    for (int o = 16; o; o >>= 1) s += __shfl_xor_sync(0xffffffffu, s, o);
    if (lane == 0) {
        if (warp < R) g_qnorm[warp] = s;
        else          g_knorm[warp - R] = s;
    }
}

// ---------------------------------------------------------------------------
// Kernel 2: scores[b,s,t] = -softplus(beta)*dist(q_s,k_t) - bias
// 64x64 tile per block, D split into 2 chunks of 64 to stay < 48KB smem.
// Strided 4x4 register tiling: thread (tx,ty) owns rows {ty+16i}, cols {tx+16j}
// -> all shared loads conflict-free, all global stores coalesced.
// ---------------------------------------------------------------------------
__global__ __launch_bounds__(256) void scores_kernel(const float* __restrict__ q,
                                                     const float* __restrict__ k,
                                                     const float* __restrict__ cp,
                                                     const float* __restrict__ betap,
                                                     const float* __restrict__ biasp,
                                                     float* __restrict__ W) {
    __shared__ float Qs[64][64];      // 16 KB
    __shared__ float KsT[64][65];     // 16.25 KB (padded: conflict-free)

    const int b = blockIdx.z;
    const int row0 = blockIdx.y * 64, col0 = blockIdx.x * 64;
    const float* qb = q + ((size_t)b * SS + row0) * DD;
    const float* kb = k + ((size_t)b * SS + col0) * DD;
    const int tid = threadIdx.x;
    const int tx = tid & 15, ty = tid >> 4;

    float acc[4][4] = {};

    for (int dch = 0; dch < DD; dch += 64) {
        // load Q chunk [64 rows x 64 d] and K chunk transposed [64 d x 64 cols]
        for (int i = tid; i < 64 * 64; i += 256) {
            int r = i >> 6, dd = i & 63;
            Qs[r][dd] = qb[r * DD + dch + dd];     // coalesced
            KsT[dd][r] = kb[r * DD + dch + dd];    // coalesced read, cf write
        }
        __syncthreads();
#pragma unroll 8
        for (int kk = 0; kk < 64; kk++) {
            float a[4], bv[4];
#pragma unroll
            for (int i = 0; i < 4; i++) a[i] = Qs[ty + 16 * i][kk];   // broadcast
#pragma unroll
            for (int j = 0; j < 4; j++) bv[j] = KsT[kk][tx + 16 * j]; // cf
#pragma unroll
            for (int i = 0; i < 4; i++)
#pragma unroll
                for (int j = 0; j < 4; j++) acc[i][j] += a[i] * bv[j];
        }
        __syncthreads();
    }

    // epilogue: Poincare distance -> attention score
    const float c = *cp;
    const float sqrtc = sqrtf(c);
    const float beta = *betap;
    const float bias = *biasp;
    const float bp = fmaxf(beta, 0.f) + log1pf(expf(-fabsf(beta)));  // softplus

#pragma unroll
    for (int i = 0; i < 4; i++) {
        const int r = row0 + ty + 16 * i;
        const float qn = g_qnorm[b * SS + r];
        const float one_m_cqn = 1.f - c * qn;
        float* wrow = W + ((size_t)b * SS + r) * SS + col0;
#pragma unroll
        for (int j = 0; j < 4; j++) {
            const int cc = col0 + tx + 16 * j;
            const float kn = g_knorm[b * SS + cc];
            const float diff = qn - 2.f * acc[i][j] + kn;
            const float denom = one_m_cqn * (1.f - c * kn);
            const float arg = 1.f + 2.f * c * diff / fmaxf(denom, EPSV);
            const float dist = acoshf(fmaxf(arg, 1.f + EPSV)) / sqrtc;
            wrow[tx + 16 * j] = -bp * dist - bias;   // coalesced
        }
    }
}

// ---------------------------------------------------------------------------
// Kernel 3: in-place row softmax. One block per row, row held in registers.
// ---------------------------------------------------------------------------
__global__ __launch_bounds__(256) void softmax_kernel(float* __restrict__ W) {
    __shared__ float red[256];
    const int r = blockIdx.x;                  // 0 .. B*S-1
    float* wr = W + (size_t)r * SS;
    const int tid = threadIdx.x;

    float vals[8];
    float m = -INFINITY;
#pragma unroll
    for (int i = 0; i < 8; i++) {
        float x = wr[tid + 256 * i];
        vals[i] = x;
        m = fmaxf(m, x);
    }
    red[tid] = m;
    __syncthreads();
    for (int s2 = 128; s2; s2 >>= 1) {
        if (tid < s2) red[tid] = fmaxf(red[tid], red[tid + s2]);
        __syncthreads();
    }
    m = red[0];
    __syncthreads();

    float sum = 0.f;
#pragma unroll
    for (int i = 0; i < 8; i++) {
        vals[i] = expf(vals[i] - m);
        sum += vals[i];
    }
    red[tid] = sum;
    __syncthreads();
    for (int s2 = 128; s2; s2 >>= 1) {
        if (tid < s2) red[tid] += red[tid + s2];
        __syncthreads();
    }
    const float inv = 1.f / red[0];

#pragma unroll
    for (int i = 0; i < 8; i++) wr[tid + 256 * i] = vals[i] * inv;
}

// ---------------------------------------------------------------------------
// Kernel 4: out = expmap0( W @ v_tangent ). 32 rows x full D=128 per block.
// Thread (tx:32, ty:8) owns rows {ty+8i}, cols {tx+32j}. Warp ty owns 4 full
// rows -> exp-map row norm via shuffle reduce, fused epilogue.
// ---------------------------------------------------------------------------
__global__ __launch_bounds__(256) void av_kernel(const float* __restrict__ W,
                                                 const float* __restrict__ v,
                                                 const float* __restrict__ cp,
                                                 float* __restrict__ out) {
    __shared__ float Ws[32][64];    // 8 KB
    __shared__ float Vs[64][128];   // 32 KB

    const int b = blockIdx.z;
    const int row0 = blockIdx.y * 32;
    const int tid = threadIdx.x;
    const int tx = tid & 31, ty = tid >> 5;

    const float* wb = W + ((size_t)b * SS + row0) * SS;
    const float* vb = v + (size_t)b * SS * DD;

    float acc[4][4] = {};

    for (int t0 = 0; t0 < SS; t0 += 64) {
        for (int i = tid; i < 32 * 64; i += 256) {
            int r = i >> 6, t = i & 63;
            Ws[r][t] = wb[(size_t)r * SS + t0 + t];   // coalesced
        }
        for (int i = tid; i < 64 * 128; i += 256) {
            int t = i >> 7, d = i & 127;
            Vs[t][d] = vb[(t0 + t) * DD + d];         // coalesced
        }
        __syncthreads();
#pragma unroll 8
        for (int t = 0; t < 64; t++) {
            float a[4], bv[4];
#pragma unroll
            for (int i = 0; i < 4; i++) a[i] = Ws[ty + 8 * i][t];     // broadcast
#pragma unroll
            for (int j = 0; j < 4; j++) bv[j] = Vs[t][tx + 32 * j];   // cf
#pragma unroll
            for (int i = 0; i < 4; i++)
#pragma unroll
                for (int j = 0; j < 4; j++) acc[i][j] += a[i] * bv[j];
        }
        __syncthreads();
    }

    // fused exp-map at origin
    const float c = *cp;
    const float sqrtc = sqrtf(c);
#pragma unroll
    for (int i = 0; i < 4; i++) {
        float ns = 0.f;
#pragma unroll
        for (int j = 0; j < 4; j++) ns += acc[i][j] * acc[i][j];
#pragma unroll
        for (int o = 16; o; o >>= 1) ns += __shfl_xor_sync(0xffffffffu, ns, o);
        const float vn = fmaxf(sqrtf(ns), EPSV);
        const float scale = tanhf(sqrtc * vn) / (sqrtc * vn);
        const int r = row0 + ty + 8 * i;
        float* orow = out + ((size_t)b * SS + r) * DD;
#pragma unroll
        for (int j = 0; j < 4; j++) orow[tx + 32 * j] = acc[i][j] * scale;
    }
}

// ---------------------------------------------------------------------------
extern "C" void kernel_launch(void* const* d_in, const int* in_sizes, int n_in,
                              void* d_out, int out_size) {
    const float* q    = (const float*)d_in[0];
    const float* k    = (const float*)d_in[1];
    const float* v    = (const float*)d_in[2];
    const float* c    = (const float*)d_in[3];
    const float* beta = (const float*)d_in[4];
    const float* bias = (const float*)d_in[5];

    float* out = (float*)d_out;                    // output_hyperbolic (B,S,D)
    float* W   = out + (size_t)BB * SS * DD;       // attention_weights (B,S,S)

    // 1) row norms: 2*B*S warps
    norms_kernel<<<(2 * BB * SS * 32 + 255) / 256, 256>>>(q, k);

    // 2) raw scores into W
    scores_kernel<<<dim3(SS / 64, SS / 64, BB), 256>>>(q, k, c, beta, bias, W);

    // 3) in-place row softmax
    softmax_kernel<<<BB * SS, 256>>>(W);

    // 4) AV GEMM + fused exp-map
    av_kernel<<<dim3(1, SS / 32, BB), 256>>>(W, v, c, out);
}

// round 5
// speedup vs baseline: 2.5724x; 2.5724x over previous
#include <cuda_runtime.h>
#include <cuda_bf16.h>
#include <cstdint>
#include <math.h>

#define BB 4
#define SSZ 2048
#define DDIM 128
#define EPSV 1e-5f

// ---------------- scratch (no allocations allowed) -------------------------
__device__ float g_qnorm[BB * SSZ];
__device__ float g_knorm[BB * SSZ];
__device__ float g_partial[BB * SSZ * 16];
__device__ float g_rowsum[BB * SSZ];
__device__ __nv_bfloat16 g_vthi[BB * DDIM * SSZ];   // V^T hi: [b][d][t]
__device__ __nv_bfloat16 g_vtlo[BB * DDIM * SSZ];   // V^T lo

// ---------------- helpers ---------------------------------------------------
__device__ __forceinline__ uint32_t smem_u32(const void* p) {
    uint32_t a;
    asm("{ .reg .u64 t; cvta.to.shared.u64 t, %1; cvt.u32.u64 %0, t; }" : "=r"(a) : "l"(p));
    return a;
}
// ldmatrix x4 (non-trans): 4 8x8 b16 matrices; operands stored k-major.
__device__ __forceinline__ void ldm_x4(uint32_t r[4], uint32_t addr) {
    asm volatile("ldmatrix.sync.aligned.m8n8.x4.shared.b16 {%0,%1,%2,%3}, [%4];"
        : "=r"(r[0]), "=r"(r[1]), "=r"(r[2]), "=r"(r[3]) : "r"(addr));
}
// D += A*B  (m16n8k16, bf16 in, f32 accum)
__device__ __forceinline__ void mma16816(float c[4], const uint32_t a[4],
                                         uint32_t b0, uint32_t b1) {
    asm volatile("mma.sync.aligned.m16n8k16.row.col.f32.bf16.bf16.f32 "
        "{%0,%1,%2,%3}, {%4,%5,%6,%7}, {%8,%9}, {%0,%1,%2,%3};"
        : "+f"(c[0]), "+f"(c[1]), "+f"(c[2]), "+f"(c[3])
        : "r"(a[0]), "r"(a[1]), "r"(a[2]), "r"(a[3]), "r"(b0), "r"(b1));
}
// split fp32 quad into bf16 hi/lo, store at element offset (padded layout)
__device__ __forceinline__ void split_store4(__nv_bfloat16* hi, __nv_bfloat16* lo,
                                             int off, float4 x) {
    __nv_bfloat162 h0 = __floats2bfloat162_rn(x.x, x.y);
    __nv_bfloat162 h1 = __floats2bfloat162_rn(x.z, x.w);
    __nv_bfloat162 l0 = __floats2bfloat162_rn(x.x - __bfloat162float(h0.x),
                                              x.y - __bfloat162float(h0.y));
    __nv_bfloat162 l1 = __floats2bfloat162_rn(x.z - __bfloat162float(h1.x),
                                              x.w - __bfloat162float(h1.y));
    *(__nv_bfloat162*)(hi + off)     = h0;
    *(__nv_bfloat162*)(hi + off + 2) = h1;
    *(__nv_bfloat162*)(lo + off)     = l0;
    *(__nv_bfloat162*)(lo + off + 2) = l1;
}

// ---------------- Kernel 1: row norms ---------------------------------------
__global__ __launch_bounds__(256) void hyp_norms(const float* __restrict__ q,
                                                 const float* __restrict__ k) {
    int warp = (blockIdx.x * blockDim.x + threadIdx.x) >> 5;
    int lane = threadIdx.x & 31;
    const int R = BB * SSZ;
    if (warp >= 2 * R) return;
    const float* src = (warp < R) ? (q + (size_t)warp * DDIM)
                                  : (k + (size_t)(warp - R) * DDIM);
    float4 v = ((const float4*)src)[lane];
    float s = v.x * v.x + v.y * v.y + v.z * v.z + v.w * v.w;
#pragma unroll
    for (int o = 16; o; o >>= 1) s += __shfl_xor_sync(0xffffffffu, s, o);
    if (lane == 0) { if (warp < R) g_qnorm[warp] = s; else g_knorm[warp - R] = s; }
}

// ---------------- Kernel 2: V^T + bf16 hi/lo split ---------------------------
__global__ void hyp_vt(const float* __restrict__ v) {
    __shared__ float tile[32][33];
    const int b = blockIdx.z, t0 = blockIdx.x * 32, d0 = blockIdx.y * 32;
    const int tx = threadIdx.x, ty = threadIdx.y;
#pragma unroll
    for (int i = 0; i < 4; i++)
        tile[ty + 8 * i][tx] = v[((size_t)(b * SSZ) + t0 + ty + 8 * i) * DDIM + d0 + tx];
    __syncthreads();
#pragma unroll
    for (int i = 0; i < 4; i++) {
        float x = tile[tx][ty + 8 * i];
        __nv_bfloat16 hi = __float2bfloat16_rn(x);
        __nv_bfloat16 lo = __float2bfloat16_rn(x - __bfloat162float(hi));
        size_t idx = ((size_t)(b * DDIM) + d0 + ty + 8 * i) * SSZ + t0 + tx;
        g_vthi[idx] = hi; g_vtlo[idx] = lo;
    }
}

// ---------------- Kernel 3: QK^T (HMMA, hi/lo x3) + hyperbolic numerator ----
// 128x128 tile / CTA, 8 warps as 2(row) x 4(col), warp tile 64x32.
// smem: qn@0 kn@512 iq@1024 ik@1536 rp@2048(2KB) | ops@4096: qhi,qlo,khi,klo
#define QPAD 136
#define QK_T (128 * QPAD)
#define QK_SMEM (4096 + 4 * QK_T * 2)
__global__ void __launch_bounds__(256, 1)
hyp_qk(const float* __restrict__ q, const float* __restrict__ k,
       const float* __restrict__ cp, const float* __restrict__ betap,
       float* __restrict__ W) {
    extern __shared__ __align__(16) char smem[];
    float* qn_s = (float*)smem;
    float* kn_s = (float*)(smem + 512);
    float* iq_s = (float*)(smem + 1024);
    float* ik_s = (float*)(smem + 1536);
    float* rp_s = (float*)(smem + 2048);
    __nv_bfloat16* qhi = (__nv_bfloat16*)(smem + 4096);
    __nv_bfloat16* qlo = qhi + QK_T;
    __nv_bfloat16* khi = qlo + QK_T;
    __nv_bfloat16* klo = khi + QK_T;

    const int tid = threadIdx.x, wid = tid >> 5, lane = tid & 31;
    const int bxx = blockIdx.x, b = blockIdx.z;
    const int row0 = blockIdx.y * 128, col0 = bxx * 128;
    const float c = *cp;

    if (tid < 128) {
        float qn = g_qnorm[b * SSZ + row0 + tid];
        float kn = g_knorm[b * SSZ + col0 + tid];
        qn_s[tid] = qn; kn_s[tid] = kn;
        iq_s[tid] = 1.f / fmaxf(1.f - c * qn, 1e-12f);
        ik_s[tid] = 1.f / fmaxf(1.f - c * kn, 1e-12f);
    }

    const float* qb = q + ((size_t)(b * SSZ + row0)) * DDIM;
    const float* kb = k + ((size_t)(b * SSZ + col0)) * DDIM;
#pragma unroll
    for (int it = 0; it < 16; it++) {
        int i = tid + 256 * it;
        int r = i >> 5, c4 = (i & 31) * 4;
        split_store4(qhi, qlo, r * QPAD + c4, *(const float4*)(qb + (size_t)r * DDIM + c4));
        split_store4(khi, klo, r * QPAD + c4, *(const float4*)(kb + (size_t)r * DDIM + c4));
    }
    __syncthreads();

    const int wr = wid >> 2, wc = wid & 3;
    const int m0 = wr * 64, n0 = wc * 32;
    const int alr = lane & 15, alc = (lane >> 4) * 8;
    uint32_t qh_a = smem_u32(qhi), ql_a = smem_u32(qlo);
    uint32_t kh_a = smem_u32(khi), kl_a = smem_u32(klo);

    float acc[4][4][4];
#pragma unroll
    for (int i = 0; i < 4; i++)
#pragma unroll
        for (int j = 0; j < 4; j++)
#pragma unroll
            for (int r = 0; r < 4; r++) acc[i][j][r] = 0.f;

#pragma unroll
    for (int ks = 0; ks < 8; ks++) {
        uint32_t ah[4][4], al[4][4], bh[2][4], bl[2][4];
        const int kel = ks * 16 + alc;
#pragma unroll
        for (int fm = 0; fm < 4; fm++) {
            uint32_t off = (uint32_t)(((m0 + fm * 16 + alr) * QPAD + kel) * 2);
            ldm_x4(ah[fm], qh_a + off);
            ldm_x4(al[fm], ql_a + off);
        }
#pragma unroll
        for (int h = 0; h < 2; h++) {
            uint32_t off = (uint32_t)(((n0 + h * 16 + alr) * QPAD + kel) * 2);
            ldm_x4(bh[h], kh_a + off);
            ldm_x4(bl[h], kl_a + off);
        }
#pragma unroll
        for (int fm = 0; fm < 4; fm++)
#pragma unroll
            for (int fn = 0; fn < 4; fn++) {
                int h = fn >> 1, s = fn & 1;
                mma16816(acc[fm][fn], ah[fm], bh[h][s], bh[h][s + 2]);
                mma16816(acc[fm][fn], ah[fm], bl[h][s], bl[h][s + 2]);
                mma16816(acc[fm][fn], al[fm], bh[h][s], bh[h][s + 2]);
            }
    }

    // epilogue: p = u^(-bp/sqrt(c)) = exp2(-(bp/sqrt(c)) * log2(u)),
    // u = (1+x) + sqrt(x(x+2)), x = 2c*diff/denom  (bias cancels in softmax)
    const float sqrtc = sqrtf(c);
    const float beta = *betap;
    const float bp = fmaxf(beta, 0.f) + log1pf(expf(-fabsf(beta)));  // softplus
    const float e2 = bp / sqrtc;                 // FIX: no ln2 factor
    const float tcc = 2.f * c;

    float* wb = W + ((size_t)(b * SSZ + row0)) * SSZ + col0;
#pragma unroll
    for (int fm = 0; fm < 4; fm++) {
        const int r1 = m0 + fm * 16 + (lane >> 2), r2 = r1 + 8;
        const float qn1 = qn_s[r1], qn2 = qn_s[r2];
        const float iq1 = iq_s[r1], iq2 = iq_s[r2];
        float s1 = 0.f, s2 = 0.f;
#pragma unroll
        for (int fn = 0; fn < 4; fn++) {
            const int cc = n0 + fn * 8 + (lane & 3) * 2;
            const float kn0 = kn_s[cc], kn1 = kn_s[cc + 1];
            const float ik0 = ik_s[cc], ik1 = ik_s[cc + 1];
            float pv[4];
#pragma unroll
            for (int rr = 0; rr < 2; rr++) {
                float qn = rr ? qn2 : qn1, iq = rr ? iq2 : iq1;
#pragma unroll
                for (int jj = 0; jj < 2; jj++) {
                    float dot = acc[fm][fn][rr * 2 + jj];
                    float kn = jj ? kn1 : kn0, ik = jj ? ik1 : ik0;
                    float x = tcc * (qn + kn - 2.f * dot) * iq * ik;
                    x = fmaxf(x, EPSV);
                    float t = x * (x + 2.f);
                    float u = (1.f + x) + t * rsqrtf(t);
                    float p = exp2f(-e2 * __log2f(u));
                    pv[rr * 2 + jj] = p;
                    if (rr) s2 += p; else s1 += p;
                }
            }
            *(float2*)(wb + (size_t)r1 * SSZ + cc) = make_float2(pv[0], pv[1]);
            *(float2*)(wb + (size_t)r2 * SSZ + cc) = make_float2(pv[2], pv[3]);
        }
        s1 += __shfl_xor_sync(0xffffffffu, s1, 1);
        s1 += __shfl_xor_sync(0xffffffffu, s1, 2);
        s2 += __shfl_xor_sync(0xffffffffu, s2, 1);
        s2 += __shfl_xor_sync(0xffffffffu, s2, 2);
        if ((lane & 3) == 0) {
            rp_s[r1 * 4 + wc] = s1;
            rp_s[r2 * 4 + wc] = s2;
        }
    }
    __syncthreads();
    if (tid < 128) {
        float s = rp_s[tid * 4] + rp_s[tid * 4 + 1] + rp_s[tid * 4 + 2] + rp_s[tid * 4 + 3];
        g_partial[((size_t)(b * SSZ + row0 + tid)) * 16 + bxx] = s;
    }
}

// ---------------- Kernel 4: reduce partials ---------------------------------
__global__ __launch_bounds__(256) void hyp_rowsum() {
    int row = blockIdx.x * 256 + threadIdx.x;
    float s = 0.f;
#pragma unroll
    for (int i = 0; i < 16; i++) s += g_partial[(size_t)row * 16 + i];
    g_rowsum[row] = s;
}

// ---------------- Kernel 5: normalize W in place ----------------------------
__global__ __launch_bounds__(256) void hyp_norm_w(float* __restrict__ W) {
    const float inv = 1.f / g_rowsum[blockIdx.x];
    float4* wr = (float4*)(W + (size_t)blockIdx.x * SSZ);
    const int t = threadIdx.x;
#pragma unroll
    for (int i = 0; i < 2; i++) {
        float4 x = wr[t + 256 * i];
        x.x *= inv; x.y *= inv; x.z *= inv; x.w *= inv;
        wr[t + 256 * i] = x;
    }
}

// ---------------- Kernel 6: O = expmap0(W @ V) (HMMA, hi/lo x3) -------------
// 64(M) x 128(N=D) tile / CTA, 8 warps 2x4, warp tile 32x32. K=2048 in 64-chunks.
// smem: rp@0(1KB) scale@1024 | ops@2048: whi,wlo[64][72], vhi,vlo[128][72]
#define APAD 72
#define AV_WT (64 * APAD)
#define AV_VT (128 * APAD)
#define AV_SMEM (2048 + (2 * AV_WT + 2 * AV_VT) * 2)
__global__ void __launch_bounds__(256, 1)
hyp_av(const float* __restrict__ W, const float* __restrict__ cp,
       float* __restrict__ out) {
    extern __shared__ __align__(16) char smem[];
    float* rp_s = (float*)smem;
    float* sc_s = (float*)(smem + 1024);
    __nv_bfloat16* whi = (__nv_bfloat16*)(smem + 2048);
    __nv_bfloat16* wlo = whi + AV_WT;
    __nv_bfloat16* vhi = wlo + AV_WT;
    __nv_bfloat16* vlo = vhi + AV_VT;

    const int tid = threadIdx.x, wid = tid >> 5, lane = tid & 31;
    const int b = blockIdx.z;
    const int row0 = blockIdx.x * 64;

    const float* wb = W + ((size_t)(b * SSZ + row0)) * SSZ;
    const __nv_bfloat16* vth = g_vthi + (size_t)b * DDIM * SSZ;
    const __nv_bfloat16* vtl = g_vtlo + (size_t)b * DDIM * SSZ;

    const int wr = wid >> 2, wc = wid & 3;
    const int m0 = wr * 32, n0 = wc * 32;
    const int alr = lane & 15, alc = (lane >> 4) * 8;
    uint32_t wh_a = smem_u32(whi), wl_a = smem_u32(wlo);
    uint32_t vh_a = smem_u32(vhi), vl_a = smem_u32(vlo);

    float acc[2][4][4];
#pragma unroll
    for (int i = 0; i < 2; i++)
#pragma unroll
        for (int j = 0; j < 4; j++)
#pragma unroll
            for (int r = 0; r < 4; r++) acc[i][j][r] = 0.f;

    for (int kc = 0; kc < 32; kc++) {
        const int t0 = kc * 64;
#pragma unroll
        for (int it = 0; it < 4; it++) {
            int i = tid + 256 * it;
            int r = i >> 4, c4 = (i & 15) * 4;
            split_store4(whi, wlo, r * APAD + c4,
                         *(const float4*)(wb + (size_t)r * SSZ + t0 + c4));
        }
#pragma unroll
        for (int it = 0; it < 4; it++) {
            int i = tid + 256 * it;
            int d = i >> 3, t8 = (i & 7) * 8;
            *(uint4*)(vhi + d * APAD + t8) = *(const uint4*)(vth + (size_t)d * SSZ + t0 + t8);
            *(uint4*)(vlo + d * APAD + t8) = *(const uint4*)(vtl + (size_t)d * SSZ + t0 + t8);
        }
        __syncthreads();
#pragma unroll
        for (int ks = 0; ks < 4; ks++) {
            uint32_t ah[2][4], al[2][4], bh[2][4], bl[2][4];
            const int kel = ks * 16 + alc;
#pragma unroll
            for (int fm = 0; fm < 2; fm++) {
                uint32_t off = (uint32_t)(((m0 + fm * 16 + alr) * APAD + kel) * 2);
                ldm_x4(ah[fm], wh_a + off);
                ldm_x4(al[fm], wl_a + off);
            }
#pragma unroll
            for (int h = 0; h < 2; h++) {
                uint32_t off = (uint32_t)(((n0 + h * 16 + alr) * APAD + kel) * 2);
                ldm_x4(bh[h], vh_a + off);
                ldm_x4(bl[h], vl_a + off);
            }
#pragma unroll
            for (int fm = 0; fm < 2; fm++)
#pragma unroll
                for (int fn = 0; fn < 4; fn++) {
                    int h = fn >> 1, s = fn & 1;
                    mma16816(acc[fm][fn], ah[fm], bh[h][s], bh[h][s + 2]);
                    mma16816(acc[fm][fn], ah[fm], bl[h][s], bl[h][s + 2]);
                    mma16816(acc[fm][fn], al[fm], bh[h][s], bh[h][s + 2]);
                }
        }
        __syncthreads();
    }

    // exp-map epilogue
#pragma unroll
    for (int fm = 0; fm < 2; fm++) {
        const int r1 = m0 + fm * 16 + (lane >> 2), r2 = r1 + 8;
        float s1 = 0.f, s2 = 0.f;
#pragma unroll
        for (int fn = 0; fn < 4; fn++) {
            s1 += acc[fm][fn][0] * acc[fm][fn][0] + acc[fm][fn][1] * acc[fm][fn][1];
            s2 += acc[fm][fn][2] * acc[fm][fn][2] + acc[fm][fn][3] * acc[fm][fn][3];
        }
        s1 += __shfl_xor_sync(0xffffffffu, s1, 1);
        s1 += __shfl_xor_sync(0xffffffffu, s1, 2);
        s2 += __shfl_xor_sync(0xffffffffu, s2, 1);
        s2 += __shfl_xor_sync(0xffffffffu, s2, 2);
        if ((lane & 3) == 0) {
            rp_s[r1 * 4 + wc] = s1;
            rp_s[r2 * 4 + wc] = s2;
        }
    }
    __syncthreads();
    const float c = *cp, sqrtc = sqrtf(c);
    if (tid < 64) {
        float ns = rp_s[tid * 4] + rp_s[tid * 4 + 1] + rp_s[tid * 4 + 2] + rp_s[tid * 4 + 3];
        float vn = fmaxf(sqrtf(ns), EPSV);
        sc_s[tid] = tanhf(sqrtc * vn) / (sqrtc * vn);
    }
    __syncthreads();

    float* ob = out + ((size_t)(b * SSZ + row0)) * DDIM;
#pragma unroll
    for (int fm = 0; fm < 2; fm++) {
        const int r1 = m0 + fm * 16 + (lane >> 2), r2 = r1 + 8;
        const float sc1 = sc_s[r1], sc2 = sc_s[r2];
#pragma unroll
        for (int fn = 0; fn < 4; fn++) {
            const int cc = n0 + fn * 8 + (lane & 3) * 2;
            *(float2*)(ob + (size_t)r1 * DDIM + cc) =
                make_float2(acc[fm][fn][0] * sc1, acc[fm][fn][1] * sc1);
            *(float2*)(ob + (size_t)r2 * DDIM + cc) =
                make_float2(acc[fm][fn][2] * sc2, acc[fm][fn][3] * sc2);
        }
    }
}

// ---------------------------------------------------------------------------
extern "C" void kernel_launch(void* const* d_in, const int* in_sizes, int n_in,
                              void* d_out, int out_size) {
    const float* q    = (const float*)d_in[0];
    const float* k    = (const float*)d_in[1];
    const float* v    = (const float*)d_in[2];
    const float* c    = (const float*)d_in[3];
    const float* beta = (const float*)d_in[4];

    float* out = (float*)d_out;                   // output_hyperbolic (B,S,D)
    float* W   = out + (size_t)BB * SSZ * DDIM;   // attention_weights (B,S,S)

    cudaFuncSetAttribute(hyp_qk, cudaFuncAttributeMaxDynamicSharedMemorySize, QK_SMEM);
    cudaFuncSetAttribute(hyp_av, cudaFuncAttributeMaxDynamicSharedMemorySize, AV_SMEM);

    hyp_norms<<<(2 * BB * SSZ * 32 + 255) / 256, 256>>>(q, k);
    hyp_vt<<<dim3(SSZ / 32, DDIM / 32, BB), dim3(32, 8)>>>(v);
    hyp_qk<<<dim3(SSZ / 128, SSZ / 128, BB), 256, QK_SMEM>>>(q, k, c, beta, W);
    hyp_rowsum<<<BB * SSZ / 256, 256>>>();
    hyp_norm_w<<<BB * SSZ, 256>>>(W);
    hyp_av<<<dim3(SSZ / 64, 1, BB), 256, AV_SMEM>>>(W, c, out);
}